// round 3
// baseline (speedup 1.0000x reference)
#include <cuda_runtime.h>

#define EE 4
#define HH 64
#define NNN 64
#define BB 8
#define LL 8
#define DDD 128
#define DIA_ 110
#define BN 512               // B*N
#define KK (DIA_*BN)         // 56320
#define NVOX (HH*NNN*NNN)    // 262144

// Scratch (static device globals — no allocation allowed)
__device__ float4 g_tab[NVOX * 2];   // 8 MB: g_tab[2v]=g[0..3], g_tab[2v+1]=g[4..7]
__device__ float  SAacc[LL * BN];    // sum over d of exp(-s)

// ---------------------------------------------------------------------------
// Kernel 1: bilinear rotation + xp slab substitution + FL-folded voxel table.
// Also zeros SAacc.
// ---------------------------------------------------------------------------
__global__ void k_rot_g(const float* __restrict__ grid,
                        const float* __restrict__ xp,
                        const float* __restrict__ theta_ls,
                        const float* __restrict__ FL,       // (E,L) row-major
                        const int*   __restrict__ theta_idx,
                        const int*   __restrict__ p_ptr)
{
    int v = blockIdx.x * blockDim.x + threadIdx.x;
    if (v < LL * BN) SAacc[v] = 0.f;
    if (v >= NVOX) return;

    int h   = v >> 12;       // / (N*N)
    int rem = v & 4095;
    int i   = rem >> 6;
    int j   = rem & 63;

    float theta = theta_ls[theta_idx[0]];
    float ct = cosf(theta), st = sinf(theta);
    const float c = (NNN - 1) * 0.5f;
    float x  = (float)j - c;
    float y  = (float)i - c;
    float xs = ct * x - st * y + c;
    float ys = st * x + ct * y + c;
    float x0f = floorf(xs), y0f = floorf(ys);
    float wx = xs - x0f, wy = ys - y0f;
    int x0 = (int)x0f, y0 = (int)y0f;

    float w00 = (1.f - wy) * (1.f - wx);
    float w01 = (1.f - wy) * wx;
    float w10 = wy * (1.f - wx);
    float w11 = wy * wx;

    float conc[EE];
#pragma unroll
    for (int e = 0; e < EE; e++) {
        const float* img = grid + ((size_t)(e * HH + h) << 12);
        float acc = 0.f;
#pragma unroll
        for (int t = 0; t < 4; t++) {
            int dy = t >> 1, dxp = t & 1;
            float w = (t == 0) ? w00 : (t == 1) ? w01 : (t == 2) ? w10 : w11;
            int yy = y0 + dy, xx = x0 + dxp;
            bool valid = (yy >= 0) && (yy < NNN) && (xx >= 0) && (xx < NNN);
            int yc = min(max(yy, 0), NNN - 1);
            int xc = min(max(xx, 0), NNN - 1);
            float val = __ldg(img + (yc << 6) + xc);
            acc += valid ? val * w : 0.f;
        }
        conc[e] = acc;
    }

    // substitute xp slab: rows [B*p, B*p+B) of the (H*N, N) view
    int row = (h << 6) + i;
    int r0  = BB * p_ptr[0];
    if (row >= r0 && row < r0 + BB) {
        int bb = row - r0;
#pragma unroll
        for (int e = 0; e < EE; e++) conc[e] = xp[(e * BB + bb) * NNN + j];
    }

    float g[LL];
#pragma unroll
    for (int l = 0; l < LL; l++) {
        float acc = 0.f;
#pragma unroll
        for (int e = 0; e < EE; e++) acc += FL[e * LL + l] * conc[e];
        g[l] = acc;
    }
    g_tab[2 * v]     = make_float4(g[0], g[1], g[2], g[3]);
    g_tab[2 * v + 1] = make_float4(g[4], g[5], g[6], g[7]);
}

// ---------------------------------------------------------------------------
// Kernel 2: main gather.  One warp per ray (d, v).  110 entries per ray.
// s[l] = sum_i P_len * g[l, P_idx]; then SAacc[l,v] += exp(-s[l]).
// ---------------------------------------------------------------------------
__global__ void __launch_bounds__(256) k_main(const int*   __restrict__ P_idx,
                                              const float* __restrict__ P_len)
{
    const unsigned FULL = 0xFFFFFFFFu;
    int gtid = blockIdx.x * blockDim.x + threadIdx.x;
    int w    = gtid >> 5;
    int lane = threadIdx.x & 31;
    int v = w & (BN - 1);
    int d = w >> 9;
    size_t base = (size_t)d * KK + (size_t)v * DIA_;

    // prefetch idx/len for all 4 strips (MLP)
    int   idxs[4];
    float lens[4];
#pragma unroll
    for (int k = 0; k < 4; k++) {
        int i = lane + k * 32;
        bool act = (i < DIA_);
        idxs[k] = act ? __ldg(P_idx + base + i) : 0;
        lens[k] = act ? __ldg(P_len + base + i) : 0.f;
    }

    float s[LL];
#pragma unroll
    for (int l = 0; l < LL; l++) s[l] = 0.f;

#pragma unroll
    for (int k = 0; k < 4; k++) {
        float4 ga = __ldg(&g_tab[2 * idxs[k]]);
        float4 gb = __ldg(&g_tab[2 * idxs[k] + 1]);
        float  ln = lens[k];
        s[0] += ln * ga.x; s[1] += ln * ga.y; s[2] += ln * ga.z; s[3] += ln * ga.w;
        s[4] += ln * gb.x; s[5] += ln * gb.y; s[6] += ln * gb.z; s[7] += ln * gb.w;
    }

    // Value-splitting warp reduction: 9 shuffles total.
    // Level 1 (xor 16): keep 4 values.  lane&16==0 keeps l=0..3, else l=4..7.
#pragma unroll
    for (int t = 0; t < 4; t++) {
        float send = (lane & 16) ? s[t] : s[t + 4];
        float r = __shfl_xor_sync(FULL, send, 16);
        s[t] = (lane & 16) ? (s[t + 4] + r) : (s[t] + r);
    }
    // Level 2 (xor 8): keep 2.
#pragma unroll
    for (int t = 0; t < 2; t++) {
        float send = (lane & 8) ? s[t] : s[t + 2];
        float r = __shfl_xor_sync(FULL, send, 8);
        s[t] = (lane & 8) ? (s[t + 2] + r) : (s[t] + r);
    }
    // Level 3 (xor 4): keep 1.
    {
        float send = (lane & 4) ? s[0] : s[1];
        float r = __shfl_xor_sync(FULL, send, 4);
        s[0] = (lane & 4) ? (s[1] + r) : (s[0] + r);
    }
    // Levels 4,5: butterfly within 4-lane group
    s[0] += __shfl_xor_sync(FULL, s[0], 2);
    s[0] += __shfl_xor_sync(FULL, s[0], 1);

    if ((lane & 3) == 0) {
        int l = ((lane >> 4) & 1) * 4 + ((lane >> 3) & 1) * 2 + ((lane >> 2) & 1);
        atomicAdd(&SAacc[l * BN + v], __expf(-s[0]));
    }
}

// ---------------------------------------------------------------------------
// Kernel 3: epilogue.  Blocks 0..63 -> out1[l,b]; block 64 -> out2[b].
// ---------------------------------------------------------------------------
__global__ void k_out(const float* __restrict__ xp,
                      const float* __restrict__ attCS,
                      const float* __restrict__ detU,
                      const int*   __restrict__ line_to_elem,
                      const float* __restrict__ scm,
                      const float* __restrict__ pcts,
                      float* __restrict__ out)
{
    __shared__ float sh[NNN];
    __shared__ float r2[2];
    int tid = threadIdx.x;
    float dx = scm[0] / (float)NNN;

    if (blockIdx.x < LL * BB) {
        int l = blockIdx.x >> 3;
        int b = blockIdx.x & 7;
        int n = tid;
        // per-column LAC summed over elements
        float A = 0.f;
#pragma unroll
        for (int e = 0; e < EE; e++) A += attCS[e] * xp[(e * BB + b) * NNN + n];
        sh[n] = A;
        __syncthreads();
        float pref = 0.f;                 // exclusive prefix
        for (int k = 0; k < n; k++) pref += sh[k];
        float att = __expf(-pref * dx);
        int le = line_to_elem[l];
        float fl = xp[(le * BB + b) * NNN + n] * detU[l];
        float SA = SAacc[l * BN + b * NNN + n] * (1.f / (float)DDD);
        float sig = pcts[0] * att * fl * SA;
        // reduce over 64 threads
#pragma unroll
        for (int off = 16; off > 0; off >>= 1)
            sig += __shfl_xor_sync(0xFFFFFFFFu, sig, off);
        if ((tid & 31) == 0) r2[tid >> 5] = sig;
        __syncthreads();
        if (tid == 0) out[l * BB + b] = r2[0] + r2[1];
    } else {
        // out2: transmission per beam row b
        int b = tid;
        if (b < BB) {
            float tot = 0.f;
            for (int n = 0; n < NNN; n++) {
                float A = 0.f;
#pragma unroll
                for (int e = 0; e < EE; e++) A += attCS[e] * xp[(e * BB + b) * NNN + n];
                tot += A;
            }
            out[64 + b] = pcts[0] * __expf(-tot * dx);
        }
    }
}

// ---------------------------------------------------------------------------
extern "C" void kernel_launch(void* const* d_in, const int* in_sizes, int n_in,
                              void* d_out, int out_size)
{
    const float* grid      = (const float*)d_in[0];   // (E,H,N,N)
    const float* xp        = (const float*)d_in[1];   // (E,B,N)
    const float* theta_ls  = (const float*)d_in[2];   // (16,)
    const float* attCS     = (const float*)d_in[3];   // (E,)
    const float* FL        = (const float*)d_in[4];   // (E,L)
    const float* detU      = (const float*)d_in[5];   // (L,)
    const float* P_len     = (const float*)d_in[6];   // (D,K)
    const float* scm       = (const float*)d_in[7];   // scalar
    const float* pcts      = (const float*)d_in[8];   // scalar
    const int*   l2e       = (const int*)d_in[9];     // (L,)
    const int*   P_idx     = (const int*)d_in[10];    // (D,K)
    const int*   th_idx    = (const int*)d_in[11];    // scalar int
    const int*   p_ptr     = (const int*)d_in[12];    // scalar int
    float* out = (float*)d_out;                        // 72 floats: out1(8,8) ++ out2(8)

    k_rot_g<<<NVOX / 256, 256>>>(grid, xp, theta_ls, FL, th_idx, p_ptr);
    // D*BN = 65536 rays, 1 warp each, 8 warps/block
    k_main<<<(DDD * BN) / 8, 256>>>(P_idx, P_len);
    k_out<<<LL * BB + 1, NNN>>>(xp, attCS, detU, l2e, scm, pcts, out);
}

// round 5
// speedup vs baseline: 1.3217x; 1.3217x over previous
#include <cuda_runtime.h>

#define EE 4
#define HH 64
#define NNN 64
#define BB 8
#define LL 8
#define DDD 128
#define DIA_ 110
#define BN 512               // B*N
#define KK (DIA_*BN)         // 56320
#define NVOX (HH*NNN*NNN)    // 262144

// Scratch (static device globals — no allocation allowed)
__device__ float4 conc_tab[NVOX];    // 4 MB: rotated concentration, 4 elements per voxel
__device__ float  SAacc[LL * BN];    // sum over d of exp(-s)

// ---------------------------------------------------------------------------
// Kernel 1: bilinear rotation + xp slab substitution -> float4 conc table.
// Also zeros SAacc.  sincos computed once per block in SMEM.
// ---------------------------------------------------------------------------
__global__ void k_rot_g(const float* __restrict__ grid,
                        const float* __restrict__ xp,
                        const float* __restrict__ theta_ls,
                        const int*   __restrict__ theta_idx,
                        const int*   __restrict__ p_ptr)
{
    __shared__ float s_ct, s_st;
    if (threadIdx.x == 0) {
        float th = __ldg(theta_ls + __ldg(theta_idx));
        float st, ct;
        __sincosf(th, &st, &ct);
        s_ct = ct; s_st = st;
    }
    __syncthreads();

    int v = blockIdx.x * blockDim.x + threadIdx.x;
    if (v < LL * BN) SAacc[v] = 0.f;

    int h   = v >> 12;       // / (N*N)
    int rem = v & 4095;
    int i   = rem >> 6;
    int j   = rem & 63;

    float ct = s_ct, st = s_st;
    const float c = (NNN - 1) * 0.5f;
    float x  = (float)j - c;
    float y  = (float)i - c;
    float xs = ct * x - st * y + c;
    float ys = st * x + ct * y + c;
    float x0f = floorf(xs), y0f = floorf(ys);
    float wx = xs - x0f, wy = ys - y0f;
    int x0 = (int)x0f, y0 = (int)y0f;

    float w00 = (1.f - wy) * (1.f - wx);
    float w01 = (1.f - wy) * wx;
    float w10 = wy * (1.f - wx);
    float w11 = wy * wx;

    float conc[EE];
#pragma unroll
    for (int e = 0; e < EE; e++) {
        const float* img = grid + ((size_t)(e * HH + h) << 12);
        float acc = 0.f;
#pragma unroll
        for (int t = 0; t < 4; t++) {
            int dy = t >> 1, dxp = t & 1;
            float w = (t == 0) ? w00 : (t == 1) ? w01 : (t == 2) ? w10 : w11;
            int yy = y0 + dy, xx = x0 + dxp;
            bool valid = (yy >= 0) && (yy < NNN) && (xx >= 0) && (xx < NNN);
            int yc = min(max(yy, 0), NNN - 1);
            int xc = min(max(xx, 0), NNN - 1);
            float val = __ldg(img + (yc << 6) + xc);
            acc += valid ? val * w : 0.f;
        }
        conc[e] = acc;
    }

    // substitute xp slab: rows [B*p, B*p+B) of the (H*N, N) view
    int row = (h << 6) + i;
    int r0  = BB * __ldg(p_ptr);
    if (row >= r0 && row < r0 + BB) {
        int bb = row - r0;
#pragma unroll
        for (int e = 0; e < EE; e++) conc[e] = __ldg(xp + (e * BB + bb) * NNN + j);
    }

    conc_tab[v] = make_float4(conc[0], conc[1], conc[2], conc[3]);
}

// ---------------------------------------------------------------------------
// Kernel 2: main gather.  One warp per ray (d, v).  110 entries per ray,
// ONE 16-byte gather per entry (per_ray accumulated in element space,
// FL applied after the warp reduction).
// ---------------------------------------------------------------------------
__global__ void __launch_bounds__(256) k_main(const int*   __restrict__ P_idx,
                                              const float* __restrict__ P_len,
                                              const float* __restrict__ FL)
{
    const unsigned FULL = 0xFFFFFFFFu;
    int gtid = blockIdx.x * blockDim.x + threadIdx.x;
    int w    = gtid >> 5;
    int lane = threadIdx.x & 31;
    int v = w & (BN - 1);
    int d = w >> 9;
    size_t base = (size_t)d * KK + (size_t)v * DIA_;

    // prefetch idx/len for all 4 strips (MLP)
    int   idxs[4];
    float lens[4];
#pragma unroll
    for (int k = 0; k < 4; k++) {
        int i = lane + k * 32;
        bool act = (i < DIA_);
        idxs[k] = act ? __ldg(P_idx + base + i) : 0;
        lens[k] = act ? __ldg(P_len + base + i) : 0.f;
    }

    float pr[EE] = {0.f, 0.f, 0.f, 0.f};
#pragma unroll
    for (int k = 0; k < 4; k++) {
        float4 g = __ldg(&conc_tab[idxs[k]]);
        float ln = lens[k];
        pr[0] += ln * g.x; pr[1] += ln * g.y;
        pr[2] += ln * g.z; pr[3] += ln * g.w;
    }

    // Value-splitting warp reduction over 4 accumulators: 6 shuffles.
    // After this, every lane in 8-lane group g holds the full-warp sum for e=g.
#pragma unroll
    for (int t = 0; t < 2; t++) {            // xor 16: keep 2 (e-pair select by bit4)
        float send = (lane & 16) ? pr[t] : pr[t + 2];
        float r = __shfl_xor_sync(FULL, send, 16);
        pr[t] = (lane & 16) ? (pr[t + 2] + r) : (pr[t] + r);
    }
    {                                        // xor 8: keep 1 (e parity by bit3)
        float send = (lane & 8) ? pr[0] : pr[1];
        float r = __shfl_xor_sync(FULL, send, 8);
        pr[0] = (lane & 8) ? (pr[1] + r) : (pr[0] + r);
    }
    pr[0] += __shfl_xor_sync(FULL, pr[0], 4);
    pr[0] += __shfl_xor_sync(FULL, pr[0], 2);
    pr[0] += __shfl_xor_sync(FULL, pr[0], 1);

    // broadcast the 4 element sums to all lanes
    float p0 = __shfl_sync(FULL, pr[0], 0);
    float p1 = __shfl_sync(FULL, pr[0], 8);
    float p2 = __shfl_sync(FULL, pr[0], 16);
    float p3 = __shfl_sync(FULL, pr[0], 24);

    if (lane < LL) {
        // s[l] = sum_e FL[e,l] * per_ray[e]
        float s = __ldg(FL + 0 * LL + lane) * p0
                + __ldg(FL + 1 * LL + lane) * p1
                + __ldg(FL + 2 * LL + lane) * p2
                + __ldg(FL + 3 * LL + lane) * p3;
        atomicAdd(&SAacc[lane * BN + v], __expf(-s));
    }
}

// ---------------------------------------------------------------------------
// Kernel 3: epilogue.  Blocks 0..63 -> out1[l,b]; block 64 -> out2[b].
// ---------------------------------------------------------------------------
__global__ void k_out(const float* __restrict__ xp,
                      const float* __restrict__ attCS,
                      const float* __restrict__ detU,
                      const int*   __restrict__ line_to_elem,
                      const float* __restrict__ scm,
                      const float* __restrict__ pcts,
                      float* __restrict__ out)
{
    __shared__ float sh[NNN];
    __shared__ float r2[2];
    int tid = threadIdx.x;
    float dx = scm[0] / (float)NNN;

    if (blockIdx.x < LL * BB) {
        int l = blockIdx.x >> 3;
        int b = blockIdx.x & 7;
        int n = tid;
        // per-column LAC summed over elements
        float A = 0.f;
#pragma unroll
        for (int e = 0; e < EE; e++) A += attCS[e] * xp[(e * BB + b) * NNN + n];
        sh[n] = A;
        __syncthreads();
        float pref = 0.f;                 // exclusive prefix
        for (int k = 0; k < n; k++) pref += sh[k];
        float att = __expf(-pref * dx);
        int le = line_to_elem[l];
        float fl = xp[(le * BB + b) * NNN + n] * detU[l];
        float SA = SAacc[l * BN + b * NNN + n] * (1.f / (float)DDD);
        float sig = pcts[0] * att * fl * SA;
        // reduce over 64 threads
#pragma unroll
        for (int off = 16; off > 0; off >>= 1)
            sig += __shfl_xor_sync(0xFFFFFFFFu, sig, off);
        if ((tid & 31) == 0) r2[tid >> 5] = sig;
        __syncthreads();
        if (tid == 0) out[l * BB + b] = r2[0] + r2[1];
    } else {
        // out2: transmission per beam row b
        int b = tid;
        if (b < BB) {
            float tot = 0.f;
            for (int n = 0; n < NNN; n++) {
                float A = 0.f;
#pragma unroll
                for (int e = 0; e < EE; e++) A += attCS[e] * xp[(e * BB + b) * NNN + n];
                tot += A;
            }
            out[64 + b] = pcts[0] * __expf(-tot * dx);
        }
    }
}

// ---------------------------------------------------------------------------
extern "C" void kernel_launch(void* const* d_in, const int* in_sizes, int n_in,
                              void* d_out, int out_size)
{
    const float* grid      = (const float*)d_in[0];   // (E,H,N,N)
    const float* xp        = (const float*)d_in[1];   // (E,B,N)
    const float* theta_ls  = (const float*)d_in[2];   // (16,)
    const float* attCS     = (const float*)d_in[3];   // (E,)
    const float* FL        = (const float*)d_in[4];   // (E,L)
    const float* detU      = (const float*)d_in[5];   // (L,)
    const float* P_len     = (const float*)d_in[6];   // (D,K)
    const float* scm       = (const float*)d_in[7];   // scalar
    const float* pcts      = (const float*)d_in[8];   // scalar
    const int*   l2e       = (const int*)d_in[9];     // (L,)
    const int*   P_idx     = (const int*)d_in[10];    // (D,K)
    const int*   th_idx    = (const int*)d_in[11];    // scalar int
    const int*   p_ptr     = (const int*)d_in[12];    // scalar int
    float* out = (float*)d_out;                        // 72 floats: out1(8,8) ++ out2(8)

    k_rot_g<<<NVOX / 256, 256>>>(grid, xp, theta_ls, th_idx, p_ptr);
    // D*BN = 65536 rays, 1 warp each, 8 warps/block
    k_main<<<(DDD * BN) / 8, 256>>>(P_idx, P_len, FL);
    k_out<<<LL * BB + 1, NNN>>>(xp, attCS, detU, l2e, scm, pcts, out);
}

// round 6
// speedup vs baseline: 1.4051x; 1.0631x over previous
#include <cuda_runtime.h>

#define EE 4
#define HH 64
#define NNN 64
#define BB 8
#define LL 8
#define DDD 128
#define DIA_ 110
#define BN 512               // B*N
#define KK (DIA_*BN)         // 56320
#define NVOX (HH*NNN*NNN)    // 262144

// Scratch (static device globals — no allocation allowed)
__device__ float4 conc_tab[NVOX];    // 4 MB: rotated concentration, 4 elements per voxel
__device__ float  SAacc[LL * BN];    // sum over d of exp(-s)

// ---------------------------------------------------------------------------
// Kernel 1: bilinear rotation + xp slab substitution -> float4 conc table.
// Two voxels (j, j+1) per thread for ILP.  Also zeros SAacc.
// ---------------------------------------------------------------------------
__global__ void __launch_bounds__(256) k_rot_g(const float* __restrict__ grid,
                        const float* __restrict__ xp,
                        const float* __restrict__ theta_ls,
                        const int*   __restrict__ theta_idx,
                        const int*   __restrict__ p_ptr)
{
    __shared__ float s_ct, s_st;
    if (threadIdx.x == 0) {
        float th = __ldg(theta_ls + __ldg(theta_idx));
        float st, ct;
        __sincosf(th, &st, &ct);
        s_ct = ct; s_st = st;
    }
    __syncthreads();

    int pair = blockIdx.x * blockDim.x + threadIdx.x;   // 0 .. NVOX/2-1
    if (pair < LL * BN) SAacc[pair] = 0.f;

    int h   = pair >> 11;        // / (N*N/2)
    int rem = pair & 2047;
    int i   = rem >> 5;
    int j0  = (rem & 31) << 1;

    float ct = s_ct, st = s_st;
    const float c = (NNN - 1) * 0.5f;
    float y  = (float)i - c;
    int row  = (h << 6) + i;
    int r0   = BB * __ldg(p_ptr);
    bool sub = (row >= r0) && (row < r0 + BB);
    int bb   = row - r0;

    float4 outv[2];
#pragma unroll
    for (int u = 0; u < 2; u++) {
        int j = j0 + u;
        float x  = (float)j - c;
        float xs = ct * x - st * y + c;
        float ys = st * x + ct * y + c;
        float x0f = floorf(xs), y0f = floorf(ys);
        float wx = xs - x0f, wy = ys - y0f;
        int x0 = (int)x0f, y0 = (int)y0f;

        float w00 = (1.f - wy) * (1.f - wx);
        float w01 = (1.f - wy) * wx;
        float w10 = wy * (1.f - wx);
        float w11 = wy * wx;

        float conc[EE];
#pragma unroll
        for (int e = 0; e < EE; e++) {
            const float* img = grid + ((size_t)(e * HH + h) << 12);
            float acc = 0.f;
#pragma unroll
            for (int t = 0; t < 4; t++) {
                int dy = t >> 1, dxp = t & 1;
                float w = (t == 0) ? w00 : (t == 1) ? w01 : (t == 2) ? w10 : w11;
                int yy = y0 + dy, xx = x0 + dxp;
                bool valid = (yy >= 0) && (yy < NNN) && (xx >= 0) && (xx < NNN);
                int yc = min(max(yy, 0), NNN - 1);
                int xc = min(max(xx, 0), NNN - 1);
                float val = __ldg(img + (yc << 6) + xc);
                acc += valid ? val * w : 0.f;
            }
            conc[e] = acc;
        }
        if (sub) {
#pragma unroll
            for (int e = 0; e < EE; e++) conc[e] = __ldg(xp + (e * BB + bb) * NNN + j);
        }
        outv[u] = make_float4(conc[0], conc[1], conc[2], conc[3]);
    }
    conc_tab[2 * pair]     = outv[0];
    conc_tab[2 * pair + 1] = outv[1];
}

// ---------------------------------------------------------------------------
// Kernel 2: main gather.  One warp per RAY-PAIR (d, v) and (d+64, v):
// 8 independent 16-byte gathers in flight per warp, one fused 8-value
// warp reduction (9 shuffles), one atomicAdd per (l) lane carrying both
// detectorlets' exp contributions.
// ---------------------------------------------------------------------------
__global__ void __launch_bounds__(256) k_main(const int*   __restrict__ P_idx,
                                              const float* __restrict__ P_len,
                                              const float* __restrict__ FL)
{
    const unsigned FULL = 0xFFFFFFFFu;
    int gtid = blockIdx.x * blockDim.x + threadIdx.x;
    int w    = gtid >> 5;            // 0 .. 32767
    int lane = threadIdx.x & 31;
    int v  = w & (BN - 1);
    int dd = w >> 9;                 // 0 .. 63
    size_t base0 = (size_t)dd * KK + (size_t)v * DIA_;
    size_t base1 = base0 + (size_t)64 * KK;

    // stream idx/len for both rays (streaming hint: zero reuse)
    int   idx0[4], idx1[4];
    float len0[4], len1[4];
#pragma unroll
    for (int k = 0; k < 4; k++) {
        int i = lane + k * 32;
        bool act = (i < DIA_);
        idx0[k] = act ? __ldcs(P_idx + base0 + i) : 0;
        idx1[k] = act ? __ldcs(P_idx + base1 + i) : 0;
        len0[k] = act ? __ldcs(P_len + base0 + i) : 0.f;
        len1[k] = act ? __ldcs(P_len + base1 + i) : 0.f;
    }

    float s[8];
#pragma unroll
    for (int l = 0; l < 8; l++) s[l] = 0.f;

#pragma unroll
    for (int k = 0; k < 4; k++) {
        float4 g0 = __ldg(&conc_tab[idx0[k]]);
        float4 g1 = __ldg(&conc_tab[idx1[k]]);
        float l0 = len0[k], l1 = len1[k];
        s[0] += l0 * g0.x; s[1] += l0 * g0.y; s[2] += l0 * g0.z; s[3] += l0 * g0.w;
        s[4] += l1 * g1.x; s[5] += l1 * g1.y; s[6] += l1 * g1.z; s[7] += l1 * g1.w;
    }

    // Value-splitting warp reduction over 8 values: 9 shuffles.
    // End state: 4-lane group g (g = bit4*4+bit3*2+bit2) holds sum of value g.
#pragma unroll
    for (int t = 0; t < 4; t++) {            // xor 16
        float send = (lane & 16) ? s[t] : s[t + 4];
        float r = __shfl_xor_sync(FULL, send, 16);
        s[t] = (lane & 16) ? (s[t + 4] + r) : (s[t] + r);
    }
#pragma unroll
    for (int t = 0; t < 2; t++) {            // xor 8
        float send = (lane & 8) ? s[t] : s[t + 2];
        float r = __shfl_xor_sync(FULL, send, 8);
        s[t] = (lane & 8) ? (s[t + 2] + r) : (s[t] + r);
    }
    {                                        // xor 4
        float send = (lane & 4) ? s[0] : s[1];
        float r = __shfl_xor_sync(FULL, send, 4);
        s[0] = (lane & 4) ? (s[1] + r) : (s[0] + r);
    }
    s[0] += __shfl_xor_sync(FULL, s[0], 2);
    s[0] += __shfl_xor_sync(FULL, s[0], 1);

    // broadcast the 8 sums: value g lives at lane 4*g
    float p0 = __shfl_sync(FULL, s[0], 0);    // ray0 e=0
    float p1 = __shfl_sync(FULL, s[0], 4);    // ray0 e=1
    float p2 = __shfl_sync(FULL, s[0], 8);    // ray0 e=2
    float p3 = __shfl_sync(FULL, s[0], 12);   // ray0 e=3
    float q0 = __shfl_sync(FULL, s[0], 16);   // ray1 e=0
    float q1 = __shfl_sync(FULL, s[0], 20);
    float q2 = __shfl_sync(FULL, s[0], 24);
    float q3 = __shfl_sync(FULL, s[0], 28);

    if (lane < LL) {
        float f0 = __ldg(FL + 0 * LL + lane);
        float f1 = __ldg(FL + 1 * LL + lane);
        float f2 = __ldg(FL + 2 * LL + lane);
        float f3 = __ldg(FL + 3 * LL + lane);
        float sa = f0 * p0 + f1 * p1 + f2 * p2 + f3 * p3;
        float sb = f0 * q0 + f1 * q1 + f2 * q2 + f3 * q3;
        atomicAdd(&SAacc[lane * BN + v], __expf(-sa) + __expf(-sb));
    }
}

// ---------------------------------------------------------------------------
// Kernel 3: epilogue.  Blocks 0..63 -> out1[l,b]; block 64 -> out2[b].
// ---------------------------------------------------------------------------
__global__ void k_out(const float* __restrict__ xp,
                      const float* __restrict__ attCS,
                      const float* __restrict__ detU,
                      const int*   __restrict__ line_to_elem,
                      const float* __restrict__ scm,
                      const float* __restrict__ pcts,
                      float* __restrict__ out)
{
    __shared__ float sh[NNN];
    __shared__ float r2[2];
    int tid = threadIdx.x;
    float dx = scm[0] / (float)NNN;

    if (blockIdx.x < LL * BB) {
        int l = blockIdx.x >> 3;
        int b = blockIdx.x & 7;
        int n = tid;
        float A = 0.f;
#pragma unroll
        for (int e = 0; e < EE; e++) A += attCS[e] * xp[(e * BB + b) * NNN + n];
        sh[n] = A;
        __syncthreads();
        float pref = 0.f;                 // exclusive prefix
        for (int k = 0; k < n; k++) pref += sh[k];
        float att = __expf(-pref * dx);
        int le = line_to_elem[l];
        float fl = xp[(le * BB + b) * NNN + n] * detU[l];
        float SA = SAacc[l * BN + b * NNN + n] * (1.f / (float)DDD);
        float sig = pcts[0] * att * fl * SA;
#pragma unroll
        for (int off = 16; off > 0; off >>= 1)
            sig += __shfl_xor_sync(0xFFFFFFFFu, sig, off);
        if ((tid & 31) == 0) r2[tid >> 5] = sig;
        __syncthreads();
        if (tid == 0) out[l * BB + b] = r2[0] + r2[1];
    } else {
        int b = tid;
        if (b < BB) {
            float tot = 0.f;
            for (int n = 0; n < NNN; n++) {
                float A = 0.f;
#pragma unroll
                for (int e = 0; e < EE; e++) A += attCS[e] * xp[(e * BB + b) * NNN + n];
                tot += A;
            }
            out[64 + b] = pcts[0] * __expf(-tot * dx);
        }
    }
}

// ---------------------------------------------------------------------------
extern "C" void kernel_launch(void* const* d_in, const int* in_sizes, int n_in,
                              void* d_out, int out_size)
{
    const float* grid      = (const float*)d_in[0];   // (E,H,N,N)
    const float* xp        = (const float*)d_in[1];   // (E,B,N)
    const float* theta_ls  = (const float*)d_in[2];   // (16,)
    const float* attCS     = (const float*)d_in[3];   // (E,)
    const float* FL        = (const float*)d_in[4];   // (E,L)
    const float* detU      = (const float*)d_in[5];   // (L,)
    const float* P_len     = (const float*)d_in[6];   // (D,K)
    const float* scm       = (const float*)d_in[7];   // scalar
    const float* pcts      = (const float*)d_in[8];   // scalar
    const int*   l2e       = (const int*)d_in[9];     // (L,)
    const int*   P_idx     = (const int*)d_in[10];    // (D,K)
    const int*   th_idx    = (const int*)d_in[11];    // scalar int
    const int*   p_ptr     = (const int*)d_in[12];    // scalar int
    float* out = (float*)d_out;                        // 72 floats: out1(8,8) ++ out2(8)

    k_rot_g<<<(NVOX / 2) / 256, 256>>>(grid, xp, theta_ls, th_idx, p_ptr);
    // 32768 ray-pair warps, 8 warps/block
    k_main<<<(DDD * BN / 2) / 8, 256>>>(P_idx, P_len, FL);
    k_out<<<LL * BB + 1, NNN>>>(xp, attCS, detU, l2e, scm, pcts, out);
}

// round 8
// speedup vs baseline: 1.4996x; 1.0673x over previous
#include <cuda_runtime.h>

#define EE 4
#define HH 64
#define NNN 64
#define BB 8
#define LL 8
#define DDD 128
#define DIA_ 110
#define BN 512               // B*N
#define KK (DIA_*BN)         // 56320
#define NVOX (HH*NNN*NNN)    // 262144

// Scratch (static device globals — no allocation allowed)
__device__ float4 conc_tab[NVOX];    // 4 MB: rotated concentration, 4 elements per voxel
__device__ float  SAacc[LL * BN];    // sum over d of exp(-s)

// ---------------------------------------------------------------------------
// Kernel 1: bilinear rotation + xp slab substitution -> float4 conc table.
// One voxel per thread (occupancy!), 16 taps front-batched (MLP=16):
// the 4 clamped offsets are shared across the 4 element planes.
// Also zeros SAacc.
// ---------------------------------------------------------------------------
__global__ void __launch_bounds__(256) k_rot_g(const float* __restrict__ grid,
                        const float* __restrict__ xp,
                        const float* __restrict__ theta_ls,
                        const int*   __restrict__ theta_idx,
                        const int*   __restrict__ p_ptr)
{
    __shared__ float s_ct, s_st;
    if (threadIdx.x == 0) {
        float th = __ldg(theta_ls + __ldg(theta_idx));
        float st, ct;
        __sincosf(th, &st, &ct);
        s_ct = ct; s_st = st;
    }
    __syncthreads();

    int v = blockIdx.x * blockDim.x + threadIdx.x;
    if (v < LL * BN) SAacc[v] = 0.f;

    int h   = v >> 12;
    int rem = v & 4095;
    int i   = rem >> 6;
    int j   = rem & 63;

    float ct = s_ct, st = s_st;
    const float c = (NNN - 1) * 0.5f;
    float x  = (float)j - c;
    float y  = (float)i - c;
    float xs = ct * x - st * y + c;
    float ys = st * x + ct * y + c;
    float x0f = floorf(xs), y0f = floorf(ys);
    float wx = xs - x0f, wy = ys - y0f;
    int x0 = (int)x0f, y0 = (int)y0f;

    // 4 shared tap offsets + masked weights
    int   off[4];
    float wgt[4];
    {
        float wv[4] = {(1.f - wy) * (1.f - wx), (1.f - wy) * wx,
                       wy * (1.f - wx),         wy * wx};
#pragma unroll
        for (int t = 0; t < 4; t++) {
            int dy = t >> 1, dxp = t & 1;
            int yy = y0 + dy, xx = x0 + dxp;
            bool valid = (yy >= 0) && (yy < NNN) && (xx >= 0) && (xx < NNN);
            int yc = min(max(yy, 0), NNN - 1);
            int xc = min(max(xx, 0), NNN - 1);
            off[t] = (yc << 6) + xc;
            wgt[t] = valid ? wv[t] : 0.f;
        }
    }

    // front-batch all 16 independent loads
    float vals[EE][4];
#pragma unroll
    for (int e = 0; e < EE; e++) {
        const float* img = grid + ((size_t)(e * HH + h) << 12);
#pragma unroll
        for (int t = 0; t < 4; t++) vals[e][t] = __ldg(img + off[t]);
    }

    float conc[EE];
#pragma unroll
    for (int e = 0; e < EE; e++) {
        float acc = 0.f;
#pragma unroll
        for (int t = 0; t < 4; t++) acc += vals[e][t] * wgt[t];
        conc[e] = acc;
    }

    // substitute xp slab: rows [B*p, B*p+B) of the (H*N, N) view
    int row = (h << 6) + i;
    int r0  = BB * __ldg(p_ptr);
    if (row >= r0 && row < r0 + BB) {
        int bb = row - r0;
#pragma unroll
        for (int e = 0; e < EE; e++) conc[e] = __ldg(xp + (e * BB + bb) * NNN + j);
    }

    conc_tab[v] = make_float4(conc[0], conc[1], conc[2], conc[3]);
}

// ---------------------------------------------------------------------------
// Kernel 2: main gather.  One warp per RAY-QUAD: rays (dd + 32r, v), r=0..3.
// 16 independent 16-byte gathers in flight per warp, one fused 16-value
// warp reduction (16 shuffles), one atomicAdd per l lane carrying all 4
// detectorlets' exp contributions.
// ---------------------------------------------------------------------------
__global__ void __launch_bounds__(256) k_main(const int*   __restrict__ P_idx,
                                              const float* __restrict__ P_len,
                                              const float* __restrict__ FL)
{
    const unsigned FULL = 0xFFFFFFFFu;
    int gtid = blockIdx.x * blockDim.x + threadIdx.x;
    int w    = gtid >> 5;            // 0 .. 16383
    int lane = threadIdx.x & 31;
    int v  = w & (BN - 1);
    int dd = w >> 9;                 // 0 .. 31

    // stream idx/len for all 4 rays (streaming hint: zero reuse)
    int   idx[4][4];
    float len[4][4];
#pragma unroll
    for (int r = 0; r < 4; r++) {
        size_t base = (size_t)(dd + 32 * r) * KK + (size_t)v * DIA_;
#pragma unroll
        for (int k = 0; k < 4; k++) {
            int i = lane + k * 32;
            bool act = (i < DIA_);
            idx[r][k] = act ? __ldcs(P_idx + base + i) : 0;
            len[r][k] = act ? __ldcs(P_len + base + i) : 0.f;
        }
    }

    float s[16];
#pragma unroll
    for (int t = 0; t < 16; t++) s[t] = 0.f;

#pragma unroll
    for (int k = 0; k < 4; k++) {
#pragma unroll
        for (int r = 0; r < 4; r++) {
            float4 g = __ldg(&conc_tab[idx[r][k]]);
            float ln = len[r][k];
            s[r * 4 + 0] += ln * g.x;
            s[r * 4 + 1] += ln * g.y;
            s[r * 4 + 2] += ln * g.z;
            s[r * 4 + 3] += ln * g.w;
        }
    }

    // Value-splitting warp reduction over 16 values: 16 shuffles.
    // After all levels, value g is held (full-warp sum) at lanes {2g, 2g+1}.
#pragma unroll
    for (int t = 0; t < 8; t++) {            // xor 16: 16 -> 8
        float send = (lane & 16) ? s[t] : s[t + 8];
        float r = __shfl_xor_sync(FULL, send, 16);
        s[t] = (lane & 16) ? (s[t + 8] + r) : (s[t] + r);
    }
#pragma unroll
    for (int t = 0; t < 4; t++) {            // xor 8: 8 -> 4
        float send = (lane & 8) ? s[t] : s[t + 4];
        float r = __shfl_xor_sync(FULL, send, 8);
        s[t] = (lane & 8) ? (s[t + 4] + r) : (s[t] + r);
    }
#pragma unroll
    for (int t = 0; t < 2; t++) {            // xor 4: 4 -> 2
        float send = (lane & 4) ? s[t] : s[t + 2];
        float r = __shfl_xor_sync(FULL, send, 4);
        s[t] = (lane & 4) ? (s[t + 2] + r) : (s[t] + r);
    }
    {                                        // xor 2: 2 -> 1
        float send = (lane & 2) ? s[0] : s[1];
        float r = __shfl_xor_sync(FULL, send, 2);
        s[0] = (lane & 2) ? (s[1] + r) : (s[0] + r);
    }
    s[0] += __shfl_xor_sync(FULL, s[0], 1);  // xor 1: finish

    // broadcast: value g = r*4 + e lives at lane 2*g
    float p[4][4];
#pragma unroll
    for (int r = 0; r < 4; r++)
#pragma unroll
        for (int e = 0; e < 4; e++)
            p[r][e] = __shfl_sync(FULL, s[0], 2 * (r * 4 + e));

    if (lane < LL) {
        float f0 = __ldg(FL + 0 * LL + lane);
        float f1 = __ldg(FL + 1 * LL + lane);
        float f2 = __ldg(FL + 2 * LL + lane);
        float f3 = __ldg(FL + 3 * LL + lane);
        float tot = 0.f;
#pragma unroll
        for (int r = 0; r < 4; r++) {
            float sv = f0 * p[r][0] + f1 * p[r][1] + f2 * p[r][2] + f3 * p[r][3];
            tot += __expf(-sv);
        }
        atomicAdd(&SAacc[lane * BN + v], tot);
    }
}

// ---------------------------------------------------------------------------
// Kernel 3: epilogue.  Blocks 0..63 -> out1[l,b]; block 64 -> out2[b].
// ---------------------------------------------------------------------------
__global__ void k_out(const float* __restrict__ xp,
                      const float* __restrict__ attCS,
                      const float* __restrict__ detU,
                      const int*   __restrict__ line_to_elem,
                      const float* __restrict__ scm,
                      const float* __restrict__ pcts,
                      float* __restrict__ out)
{
    __shared__ float sh[NNN];
    __shared__ float r2[2];
    int tid = threadIdx.x;
    float dx = scm[0] / (float)NNN;

    if (blockIdx.x < LL * BB) {
        int l = blockIdx.x >> 3;
        int b = blockIdx.x & 7;
        int n = tid;
        float A = 0.f;
#pragma unroll
        for (int e = 0; e < EE; e++) A += attCS[e] * xp[(e * BB + b) * NNN + n];
        sh[n] = A;
        __syncthreads();
        float pref = 0.f;                 // exclusive prefix
        for (int k = 0; k < n; k++) pref += sh[k];
        float att = __expf(-pref * dx);
        int le = line_to_elem[l];
        float fl = xp[(le * BB + b) * NNN + n] * detU[l];
        float SA = SAacc[l * BN + b * NNN + n] * (1.f / (float)DDD);
        float sig = pcts[0] * att * fl * SA;
#pragma unroll
        for (int off = 16; off > 0; off >>= 1)
            sig += __shfl_xor_sync(0xFFFFFFFFu, sig, off);
        if ((tid & 31) == 0) r2[tid >> 5] = sig;
        __syncthreads();
        if (tid == 0) out[l * BB + b] = r2[0] + r2[1];
    } else {
        int b = tid;
        if (b < BB) {
            float tot = 0.f;
            for (int n = 0; n < NNN; n++) {
                float A = 0.f;
#pragma unroll
                for (int e = 0; e < EE; e++) A += attCS[e] * xp[(e * BB + b) * NNN + n];
                tot += A;
            }
            out[64 + b] = pcts[0] * __expf(-tot * dx);
        }
    }
}

// ---------------------------------------------------------------------------
extern "C" void kernel_launch(void* const* d_in, const int* in_sizes, int n_in,
                              void* d_out, int out_size)
{
    const float* grid      = (const float*)d_in[0];   // (E,H,N,N)
    const float* xp        = (const float*)d_in[1];   // (E,B,N)
    const float* theta_ls  = (const float*)d_in[2];   // (16,)
    const float* attCS     = (const float*)d_in[3];   // (E,)
    const float* FL        = (const float*)d_in[4];   // (E,L)
    const float* detU      = (const float*)d_in[5];   // (L,)
    const float* P_len     = (const float*)d_in[6];   // (D,K)
    const float* scm       = (const float*)d_in[7];   // scalar
    const float* pcts      = (const float*)d_in[8];   // scalar
    const int*   l2e       = (const int*)d_in[9];     // (L,)
    const int*   P_idx     = (const int*)d_in[10];    // (D,K)
    const int*   th_idx    = (const int*)d_in[11];    // scalar int
    const int*   p_ptr     = (const int*)d_in[12];    // scalar int
    float* out = (float*)d_out;                        // 72 floats: out1(8,8) ++ out2(8)

    k_rot_g<<<NVOX / 256, 256>>>(grid, xp, theta_ls, th_idx, p_ptr);
    // 16384 ray-quad warps, 8 warps/block
    k_main<<<(DDD * BN / 4) / 8, 256>>>(P_idx, P_len, FL);
    k_out<<<LL * BB + 1, NNN>>>(xp, attCS, detU, l2e, scm, pcts, out);
}

// round 9
// speedup vs baseline: 1.5096x; 1.0066x over previous
#include <cuda_runtime.h>

#define EE 4
#define HH 64
#define NNN 64
#define BB 8
#define LL 8
#define DDD 128
#define DIA_ 110
#define BN 512               // B*N
#define KK (DIA_*BN)         // 56320
#define NVOX (HH*NNN*NNN)    // 262144

// Scratch (static device globals — no allocation allowed)
__device__ float4 conc_tab[NVOX];    // 4 MB: rotated concentration, 4 elements per voxel
__device__ float  SAacc[LL * BN];    // sum over d of exp(-s)

// ---------------------------------------------------------------------------
// Kernel 1: bilinear rotation + xp slab substitution -> float4 conc table.
// One voxel per thread, 16 taps front-batched (offsets shared across the 4
// element planes).  sincos per-thread (2 MUFU ops, no barrier).  Zeros SAacc.
// ---------------------------------------------------------------------------
__global__ void __launch_bounds__(256) k_rot_g(const float* __restrict__ grid,
                        const float* __restrict__ xp,
                        const float* __restrict__ theta_ls,
                        const int*   __restrict__ theta_idx,
                        const int*   __restrict__ p_ptr)
{
    int v = blockIdx.x * blockDim.x + threadIdx.x;
    if (v < LL * BN) SAacc[v] = 0.f;

    int h   = v >> 12;
    int rem = v & 4095;
    int i   = rem >> 6;
    int j   = rem & 63;

    float th = __ldg(theta_ls + __ldg(theta_idx));
    float st, ct;
    __sincosf(th, &st, &ct);

    const float c = (NNN - 1) * 0.5f;
    float x  = (float)j - c;
    float y  = (float)i - c;
    float xs = ct * x - st * y + c;
    float ys = st * x + ct * y + c;
    float x0f = floorf(xs), y0f = floorf(ys);
    float wx = xs - x0f, wy = ys - y0f;
    int x0 = (int)x0f, y0 = (int)y0f;

    // 4 shared tap offsets + masked weights
    int   off[4];
    float wgt[4];
    {
        float wv[4] = {(1.f - wy) * (1.f - wx), (1.f - wy) * wx,
                       wy * (1.f - wx),         wy * wx};
#pragma unroll
        for (int t = 0; t < 4; t++) {
            int dy = t >> 1, dxp = t & 1;
            int yy = y0 + dy, xx = x0 + dxp;
            bool valid = (yy >= 0) && (yy < NNN) && (xx >= 0) && (xx < NNN);
            int yc = min(max(yy, 0), NNN - 1);
            int xc = min(max(xx, 0), NNN - 1);
            off[t] = (yc << 6) + xc;
            wgt[t] = valid ? wv[t] : 0.f;
        }
    }

    // front-batch all 16 independent loads
    float vals[EE][4];
#pragma unroll
    for (int e = 0; e < EE; e++) {
        const float* img = grid + ((size_t)(e * HH + h) << 12);
#pragma unroll
        for (int t = 0; t < 4; t++) vals[e][t] = __ldg(img + off[t]);
    }

    float conc[EE];
#pragma unroll
    for (int e = 0; e < EE; e++) {
        float acc = 0.f;
#pragma unroll
        for (int t = 0; t < 4; t++) acc += vals[e][t] * wgt[t];
        conc[e] = acc;
    }

    // substitute xp slab: rows [B*p, B*p+B) of the (H*N, N) view
    int row = (h << 6) + i;
    int r0  = BB * __ldg(p_ptr);
    if (row >= r0 && row < r0 + BB) {
        int bb = row - r0;
#pragma unroll
        for (int e = 0; e < EE; e++) conc[e] = __ldg(xp + (e * BB + bb) * NNN + j);
    }

    conc_tab[v] = make_float4(conc[0], conc[1], conc[2], conc[3]);
}

// ---------------------------------------------------------------------------
// Kernel 2: main gather.  One warp per RAY-QUAD: rays (dd + 32r, v), r=0..3.
// Streams loaded as int2/float2 (8B-aligned: v*DIA even) — 16 stream LDGs
// per warp instead of 32.  DIA=110 = 2*55 pairs: strip 0 = lanes 0..31,
// strip 1 = lanes 0..22.  16 gather LDG.128 in flight, fused 16-value
// warp reduction, one atomicAdd per l lane for all 4 detectorlets.
// ---------------------------------------------------------------------------
__global__ void __launch_bounds__(128) k_main(const int*   __restrict__ P_idx,
                                              const float* __restrict__ P_len,
                                              const float* __restrict__ FL)
{
    const unsigned FULL = 0xFFFFFFFFu;
    int gtid = blockIdx.x * blockDim.x + threadIdx.x;
    int w    = gtid >> 5;            // 0 .. 16383
    int lane = threadIdx.x & 31;
    int v  = w & (BN - 1);
    int dd = w >> 9;                 // 0 .. 31
    bool act1 = (lane < 23);         // strip-1 pairs: lane+32 < 55

    // stream idx/len pairs for all 4 rays (streaming hint: zero reuse)
    int2   ip[4][2];
    float2 lp[4][2];
#pragma unroll
    for (int r = 0; r < 4; r++) {
        size_t base = (size_t)(dd + 32 * r) * KK + (size_t)v * DIA_;
        const int2*   pi = (const int2*)(P_idx + base);
        const float2* pl = (const float2*)(P_len + base);
        ip[r][0] = __ldcs(pi + lane);
        lp[r][0] = __ldcs(pl + lane);
        if (act1) { ip[r][1] = __ldcs(pi + 32 + lane); lp[r][1] = __ldcs(pl + 32 + lane); }
        else      { ip[r][1] = make_int2(0, 0);        lp[r][1] = make_float2(0.f, 0.f); }
    }

    float s[16];
#pragma unroll
    for (int t = 0; t < 16; t++) s[t] = 0.f;

#pragma unroll
    for (int m = 0; m < 2; m++) {
#pragma unroll
        for (int half = 0; half < 2; half++) {
#pragma unroll
            for (int r = 0; r < 4; r++) {
                int   id = half ? ip[r][m].y : ip[r][m].x;
                float ln = half ? lp[r][m].y : lp[r][m].x;
                float4 g = __ldg(&conc_tab[id]);
                s[r * 4 + 0] += ln * g.x;
                s[r * 4 + 1] += ln * g.y;
                s[r * 4 + 2] += ln * g.z;
                s[r * 4 + 3] += ln * g.w;
            }
        }
    }

    // Value-splitting warp reduction over 16 values: 16 shuffles.
#pragma unroll
    for (int t = 0; t < 8; t++) {            // xor 16: 16 -> 8
        float send = (lane & 16) ? s[t] : s[t + 8];
        float r = __shfl_xor_sync(FULL, send, 16);
        s[t] = (lane & 16) ? (s[t + 8] + r) : (s[t] + r);
    }
#pragma unroll
    for (int t = 0; t < 4; t++) {            // xor 8: 8 -> 4
        float send = (lane & 8) ? s[t] : s[t + 4];
        float r = __shfl_xor_sync(FULL, send, 8);
        s[t] = (lane & 8) ? (s[t + 4] + r) : (s[t] + r);
    }
#pragma unroll
    for (int t = 0; t < 2; t++) {            // xor 4: 4 -> 2
        float send = (lane & 4) ? s[t] : s[t + 2];
        float r = __shfl_xor_sync(FULL, send, 4);
        s[t] = (lane & 4) ? (s[t + 2] + r) : (s[t] + r);
    }
    {                                        // xor 2: 2 -> 1
        float send = (lane & 2) ? s[0] : s[1];
        float r = __shfl_xor_sync(FULL, send, 2);
        s[0] = (lane & 2) ? (s[1] + r) : (s[0] + r);
    }
    s[0] += __shfl_xor_sync(FULL, s[0], 1);  // xor 1: finish

    // broadcast: value g = r*4 + e lives at lane 2*g
    float p[4][4];
#pragma unroll
    for (int r = 0; r < 4; r++)
#pragma unroll
        for (int e = 0; e < 4; e++)
            p[r][e] = __shfl_sync(FULL, s[0], 2 * (r * 4 + e));

    if (lane < LL) {
        float f0 = __ldg(FL + 0 * LL + lane);
        float f1 = __ldg(FL + 1 * LL + lane);
        float f2 = __ldg(FL + 2 * LL + lane);
        float f3 = __ldg(FL + 3 * LL + lane);
        float tot = 0.f;
#pragma unroll
        for (int r = 0; r < 4; r++) {
            float sv = f0 * p[r][0] + f1 * p[r][1] + f2 * p[r][2] + f3 * p[r][3];
            tot += __expf(-sv);
        }
        atomicAdd(&SAacc[lane * BN + v], tot);
    }
}

// ---------------------------------------------------------------------------
// Kernel 3: epilogue.  Blocks 0..63 -> out1[l,b]; block 64 -> out2[b].
// ---------------------------------------------------------------------------
__global__ void k_out(const float* __restrict__ xp,
                      const float* __restrict__ attCS,
                      const float* __restrict__ detU,
                      const int*   __restrict__ line_to_elem,
                      const float* __restrict__ scm,
                      const float* __restrict__ pcts,
                      float* __restrict__ out)
{
    __shared__ float sh[NNN];
    __shared__ float r2[2];
    int tid = threadIdx.x;
    float dx = scm[0] / (float)NNN;

    if (blockIdx.x < LL * BB) {
        int l = blockIdx.x >> 3;
        int b = blockIdx.x & 7;
        int n = tid;
        float A = 0.f;
#pragma unroll
        for (int e = 0; e < EE; e++) A += attCS[e] * xp[(e * BB + b) * NNN + n];
        sh[n] = A;
        __syncthreads();
        float pref = 0.f;                 // exclusive prefix
        for (int k = 0; k < n; k++) pref += sh[k];
        float att = __expf(-pref * dx);
        int le = line_to_elem[l];
        float fl = xp[(le * BB + b) * NNN + n] * detU[l];
        float SA = SAacc[l * BN + b * NNN + n] * (1.f / (float)DDD);
        float sig = pcts[0] * att * fl * SA;
#pragma unroll
        for (int off = 16; off > 0; off >>= 1)
            sig += __shfl_xor_sync(0xFFFFFFFFu, sig, off);
        if ((tid & 31) == 0) r2[tid >> 5] = sig;
        __syncthreads();
        if (tid == 0) out[l * BB + b] = r2[0] + r2[1];
    } else {
        int b = tid;
        if (b < BB) {
            float tot = 0.f;
            for (int n = 0; n < NNN; n++) {
                float A = 0.f;
#pragma unroll
                for (int e = 0; e < EE; e++) A += attCS[e] * xp[(e * BB + b) * NNN + n];
                tot += A;
            }
            out[64 + b] = pcts[0] * __expf(-tot * dx);
        }
    }
}

// ---------------------------------------------------------------------------
extern "C" void kernel_launch(void* const* d_in, const int* in_sizes, int n_in,
                              void* d_out, int out_size)
{
    const float* grid      = (const float*)d_in[0];   // (E,H,N,N)
    const float* xp        = (const float*)d_in[1];   // (E,B,N)
    const float* theta_ls  = (const float*)d_in[2];   // (16,)
    const float* attCS     = (const float*)d_in[3];   // (E,)
    const float* FL        = (const float*)d_in[4];   // (E,L)
    const float* detU      = (const float*)d_in[5];   // (L,)
    const float* P_len     = (const float*)d_in[6];   // (D,K)
    const float* scm       = (const float*)d_in[7];   // scalar
    const float* pcts      = (const float*)d_in[8];   // scalar
    const int*   l2e       = (const int*)d_in[9];     // (L,)
    const int*   P_idx     = (const int*)d_in[10];    // (D,K)
    const int*   th_idx    = (const int*)d_in[11];    // scalar int
    const int*   p_ptr     = (const int*)d_in[12];    // scalar int
    float* out = (float*)d_out;                        // 72 floats: out1(8,8) ++ out2(8)

    k_rot_g<<<NVOX / 256, 256>>>(grid, xp, theta_ls, th_idx, p_ptr);
    // 16384 ray-quad warps, 4 warps/block for finer tail balance
    k_main<<<(DDD * BN / 4) / 4, 128>>>(P_idx, P_len, FL);
    k_out<<<LL * BB + 1, NNN>>>(xp, attCS, detU, l2e, scm, pcts, out);
}